// round 9
// baseline (speedup 1.0000x reference)
#include <cuda_runtime.h>
#include <math.h>

#define BATCH   32
#define H       384
#define KK      378
#define NS      7
#define NSHIFT  49
#define TILE    54
#define PATCH   60
#define NTOT_D  4572288.0

#define STATS_BLOCKS  1568          // 7*7*32
#define ROWS_TOTAL    (BATCH * H)   // 12288
#define ROW_BLOCKS    1756          // ceil(12288 / 7)
#define MAIN_BLOCKS   (STATS_BLOCKS + ROW_BLOCKS)
#define ZB            1184          // zcorr blocks
#define ZGROUPS       (ZB * 4)      // 64-thread groups
#define ZW_BLOCKS     (ZB + 28)
#define MAE_BLOCKS    1512          // 12096 rows / 8 warps

// ---------------- global scratch (no allocations allowed) ----------------
// All zero at module load; the mae last block re-zeroes everything at the end
// of every run so each graph replay starts from identical state.
__device__ double g_tp[NSHIFT];            // dense cross: sum t*p per shift
__device__ double g_zp[NSHIFT];            // sparse cross: sum z*p per shift
__device__ double g_win[NSHIFT * 4];       // windowed sums: t, t^2, m, m*t
__device__ double g_sp[32];                // global sum p (spread slots)
__device__ double g_sp2[32];               // global sum p^2 (spread slots)
__device__ double g_abs[32];               // MAE accumulation (spread slots)
__device__ int    g_idx;
__device__ unsigned int g_zcount;
__device__ unsigned int g_done_zw;
__device__ unsigned int g_done_mae;
__device__ float  g_W[4 * NS * BATCH * H]; // per-row windowed sums [f][v][b][y]
__device__ int    g_zlist[BATCH * H * H];  // worst-case capacity

// ======== fused main kernel: stats blocks + rowsum blocks ========
__global__ __launch_bounds__(224) void main_kernel(
    const float* __restrict__ pred, const float* __restrict__ target)
{
    __shared__ float sT[PATCH * PATCH];
    __shared__ float sP[TILE * TILE];

    const int tid  = threadIdx.x;
    const int lane = tid & 31;
    const int wid  = tid >> 5;

    if (blockIdx.x < STATS_BLOCKS) {
        // ---- dense cross-correlation: warp = v shift, lane = column,
        //      7-row t window in registers, FULLY UNROLLED (no window MOVs) ----
        const int bid = blockIdx.x;
        const int tx = bid % 7;
        const int ty = (bid / 7) % 7;
        const int b  = bid / 49;
        const int x0 = tx * TILE;
        const int y0 = ty * TILE;
        const float* tb = target + (size_t)b * H * H;
        const float* pb = pred   + (size_t)b * H * H;

        for (int k = tid; k < PATCH * PATCH; k += 224) {
            int yy = k / PATCH, xx = k - yy * PATCH;
            sT[k] = tb[(y0 + yy) * H + (x0 + xx)];
        }
        for (int k = tid; k < TILE * TILE; k += 224) {
            int i = k / TILE, j = k - i * TILE;
            sP[k] = pb[(y0 + i + 3) * H + (x0 + j + 3)];
        }
        __syncthreads();

        const int v = wid;                     // this warp's v shift
        const bool two = (lane < TILE - 32);   // lanes 0..21 own a 2nd column
        const int c0 = lane;
        const int c1 = two ? lane + 32 : 0;

        const float* tcol0 = &sT[c0 + v];
        const float* tcol1 = &sT[c1 + v];
        const float* pcol0 = &sP[c0];
        const float* pcol1 = &sP[c1];

        float acc[NS];
#pragma unroll
        for (int u = 0; u < NS; u++) acc[u] = 0.f;

        float ta[NS], tbv[NS];
#pragma unroll
        for (int k = 0; k < 6; k++) {
            ta[k]  = tcol0[k * PATCH];
            tbv[k] = tcol1[k * PATCH];
        }

#pragma unroll
        for (int i = 0; i < TILE; i++) {
            ta[6]  = tcol0[(i + 6) * PATCH];
            tbv[6] = tcol1[(i + 6) * PATCH];
            float p0 = pcol0[i * TILE];
            float p1 = two ? pcol1[i * TILE] : 0.f;
#pragma unroll
            for (int u = 0; u < NS; u++) {
                acc[u] = fmaf(ta[u],  p0, acc[u]);
                acc[u] = fmaf(tbv[u], p1, acc[u]);
            }
#pragma unroll
            for (int k = 0; k < 6; k++) { ta[k] = ta[k + 1]; tbv[k] = tbv[k + 1]; }
        }

#pragma unroll
        for (int u = 0; u < NS; u++) {
            float tp = acc[u];
            for (int o = 16; o; o >>= 1)
                tp += __shfl_xor_sync(0xffffffffu, tp, o);
            if (lane == 0)
                atomicAdd(&g_tp[u * NS + v], (double)tp);
        }
    } else {
        // ---- per-row windowed sums + pred sums + z compaction ----
        const int gw = (blockIdx.x - STATS_BLOCKS) * 7 + wid;
        if (gw >= ROWS_TOTAL) return;
        const int b = gw / H;
        const int y = gw - b * H;
        const float* row = target + ((size_t)b * H + y) * H;

        float s0 = 0.f, s1 = 0.f, s2 = 0.f, s3 = 0.f;
        unsigned zm = 0u;
#pragma unroll
        for (int k = 0; k < 12; k++) {
            int x = lane + 32 * k;
            float t = row[x];
            float m = (t > 5.f) ? 1.f : 0.f;
            s0 += t;
            s1  = fmaf(t, t, s1);
            s2 += m;
            s3  = fmaf(m, t, s3);
            if (t <= 5.f) zm |= (1u << k);
        }

        // compact z pixels: one atomic per row
        {
            unsigned cnt = (unsigned)__popc(zm);
            unsigned pre = cnt;
            for (int o = 1; o < 32; o <<= 1) {
                unsigned n = __shfl_up_sync(0xffffffffu, pre, o);
                if (lane >= o) pre += n;
            }
            unsigned tot  = __shfl_sync(0xffffffffu, pre, 31);
            unsigned excl = pre - cnt;
            unsigned base = 0;
            if (tot) {
                if (lane == 31) base = atomicAdd(&g_zcount, tot);
                base = __shfl_sync(0xffffffffu, base, 31);
                unsigned idx = base + excl;
                unsigned mm = zm;
                while (mm) {
                    int k = __ffs(mm) - 1;
                    mm &= mm - 1;
                    g_zlist[idx++] = (b * H + y) * H + lane + 32 * k;
                }
            }
        }

        for (int o = 16; o; o >>= 1) {
            s0 += __shfl_xor_sync(0xffffffffu, s0, o);
            s1 += __shfl_xor_sync(0xffffffffu, s1, o);
            s2 += __shfl_xor_sync(0xffffffffu, s2, o);
            s3 += __shfl_xor_sync(0xffffffffu, s3, o);
        }

        if (lane == 0) {
            float e[12];
#pragma unroll
            for (int k = 0; k < 6; k++) { e[k] = row[k]; e[6 + k] = row[378 + k]; }
#pragma unroll
            for (int v = 0; v < NS; v++) {
                float L0 = 0.f, L1 = 0.f, L2 = 0.f, L3 = 0.f;
                for (int x = 0; x < v; x++) {
                    float t = e[x];
                    float m = (t > 5.f) ? 1.f : 0.f;
                    L0 += t; L1 += t * t; L2 += m; L3 += m * t;
                }
                float R0 = 0.f, R1 = 0.f, R2 = 0.f, R3 = 0.f;
                for (int k = v; k < 6; k++) {
                    float t = e[6 + k];
                    float m = (t > 5.f) ? 1.f : 0.f;
                    R0 += t; R1 += t * t; R2 += m; R3 += m * t;
                }
                g_W[((0 * NS + v) * BATCH + b) * H + y] = s0 - L0 - R0;
                g_W[((1 * NS + v) * BATCH + b) * H + y] = s1 - L1 - R1;
                g_W[((2 * NS + v) * BATCH + b) * H + y] = s2 - L2 - R2;
                g_W[((3 * NS + v) * BATCH + b) * H + y] = s3 - L3 - R3;
            }
        }

        if (y >= 3 && y < 381) {
            const float* prow = pred + ((size_t)b * H + y) * H;
            float sp = 0.f, sp2 = 0.f;
#pragma unroll
            for (int k = 0; k < 12; k++) {
                int x = 3 + lane + 32 * k;
                if (x < 381) {
                    float p = prow[x];
                    sp += p;
                    sp2 = fmaf(p, p, sp2);
                }
            }
            for (int o = 16; o; o >>= 1) {
                sp  += __shfl_xor_sync(0xffffffffu, sp,  o);
                sp2 += __shfl_xor_sync(0xffffffffu, sp2, o);
            }
            if (lane == 0) {
                atomicAdd(&g_sp [gw & 31], (double)sp);
                atomicAdd(&g_sp2[gw & 31], (double)sp2);
            }
        }
    }
}

// ======== fused: zcorr blocks + winsum blocks + last-block argmin ========
__global__ __launch_bounds__(256) void zw_kernel(const float* __restrict__ pred,
                                                 float* out)
{
    __shared__ float  sAcc[64];
    __shared__ double col[H];
    __shared__ double red[256];
    __shared__ double scmse[64];
    __shared__ int    sidx[64];
    __shared__ int    sLast;

    const int tid = threadIdx.x;

    if (blockIdx.x < ZB) {
        // ---- sparse correction: shift-per-thread, 2-deep pipelined loads ----
        if (tid < 64) sAcc[tid] = 0.f;
        __syncthreads();

        const int sid = tid & 63;
        const int u = sid / NS, v = sid - (sid / NS) * NS;
        const bool active = sid < NSHIFT;
        const int grp = (blockIdx.x * 256 + tid) >> 6;
        const int count = (int)g_zcount;

        float acc = 0.f;
        int zi = grp;
        for (; zi + ZGROUPS < count; zi += 2 * ZGROUPS) {
            int code0 = g_zlist[zi];
            int code1 = g_zlist[zi + ZGROUPS];
            int b0 = code0 / (H * H), r0 = code0 - b0 * (H * H);
            int y0 = r0 / H,          x0 = r0 - y0 * H;
            int b1 = code1 / (H * H), r1 = code1 - b1 * (H * H);
            int y1 = r1 / H,          x1 = r1 - y1 * H;
            if (active) {
                int yy0 = y0 - u, xx0 = x0 - v;
                int yy1 = y1 - u, xx1 = x1 - v;
                bool ok0 = (yy0 >= 0 && yy0 < KK && xx0 >= 0 && xx0 < KK);
                bool ok1 = (yy1 >= 0 && yy1 < KK && xx1 >= 0 && xx1 < KK);
                float p0 = ok0 ? pred[(size_t)b0 * H * H + (yy0 + 3) * H + (xx0 + 3)] : 0.f;
                float p1 = ok1 ? pred[(size_t)b1 * H * H + (yy1 + 3) * H + (xx1 + 3)] : 0.f;
                acc += p0 + p1;
            }
        }
        for (; zi < count; zi += ZGROUPS) {
            int code = g_zlist[zi];
            int b = code / (H * H);
            int r = code - b * (H * H);
            int y = r / H;
            int x = r - y * H;
            if (active) {
                int yy = y - u, xx = x - v;
                if (yy >= 0 && yy < KK && xx >= 0 && xx < KK)
                    acc += pred[(size_t)b * H * H + (yy + 3) * H + (xx + 3)];
            }
        }
        if (active && acc != 0.f) atomicAdd(&sAcc[sid], acc);
        __syncthreads();
        if (tid < NSHIFT && sAcc[tid] != 0.f)
            atomicAdd(&g_zp[tid], (double)sAcc[tid]);
    } else {
        // ---- combine per-row windowed sums: block per (f, v) ----
        const int wb = blockIdx.x - ZB;
        const int f = wb / NS;
        const int v = wb - f * NS;
        const float* Wfv = &g_W[((f * NS + v) * BATCH) * H];

        for (int y = tid; y < H; y += 256) {
            double s = 0.0;
#pragma unroll 4
            for (int b = 0; b < BATCH; b++)
                s += (double)Wfv[b * H + y];
            col[y] = s;
        }
        __syncthreads();

        double s = col[tid];
        if (tid + 256 < H) s += col[tid + 256];
        red[tid] = s;
        __syncthreads();
        for (int o = 128; o; o >>= 1) {
            if (tid < o) red[tid] += red[tid + o];
            __syncthreads();
        }
        if (tid < NS) {
            double T = red[0];
            for (int y = 0; y < tid; y++) T -= col[y];
            for (int y = tid + KK; y < H; y++) T -= col[y];
            g_win[(tid * NS + v) * 4 + f] = T;
        }
    }

    // ---- last block performs argmin + cPSNR ----
    __threadfence();
    __syncthreads();
    if (tid == 0)
        sLast = (atomicAdd(&g_done_zw, 1u) == (unsigned)(gridDim.x - 1));
    __syncthreads();
    if (!sLast) return;

    volatile double* vtp  = g_tp;
    volatile double* vzp  = g_zp;
    volatile double* vwin = g_win;
    volatile double* vsp  = g_sp;
    volatile double* vsp2 = g_sp2;

    double Sp = 0.0, Sp2 = 0.0;
    for (int k = 0; k < 32; k++) { Sp += vsp[k]; Sp2 += vsp2[k]; }

    if (tid < 64) {
        double c = 1e300;
        if (tid < NSHIFT) {
            double wt  = vwin[tid * 4 + 0];
            double wt2 = vwin[tid * 4 + 1];
            double n   = vwin[tid * 4 + 2];
            double wmt = vwin[tid * 4 + 3];
            double Sd  = wt - Sp;
            double Sd2 = wt2 - 2.0 * vtp[tid] + Sp2;
            double Sm  = wmt - (Sp - vzp[tid]);
            double bb  = Sm / n;
            c = (Sd2 - 2.0 * bb * Sd + NTOT_D * bb * bb) / n;
        }
        scmse[tid] = c; sidx[tid] = tid;
    }
    __syncthreads();
    for (int o = 32; o; o >>= 1) {
        if (tid < o) {
            if (scmse[tid + o] < scmse[tid]) {
                scmse[tid] = scmse[tid + o];
                sidx[tid]  = sidx[tid + o];
            }
        }
        __syncthreads();
    }
    if (tid == 0) {
        g_idx  = sidx[0];
        out[0] = (float)(-10.0 * log10(scmse[0]));
    }
}

// ======== MAE over winning shift + last-block finalize & self-clean ========
__global__ __launch_bounds__(256) void mae_kernel(
    const float* __restrict__ pred, const float* __restrict__ target, float* out)
{
    const int idx = g_idx;
    const int u = idx / NS, v = idx - (idx / NS) * NS;
    const int gw   = blockIdx.x * 8 + (threadIdx.x >> 5);   // 0 .. 12095
    const int lane = threadIdx.x & 31;
    const int b    = gw / KK;
    const int i    = gw - b * KK;

    const float* prow = pred   + ((size_t)b * H + i + 3) * H + 3;
    const float* trow = target + ((size_t)b * H + i + u) * H + v;

    // fully unrolled: 378 = 32*11 + 26; two accumulators for ILP
    float a0 = 0.f, a1 = 0.f;
#pragma unroll
    for (int k = 0; k < 11; k++) {
        int x = lane + 32 * k;
        float d = fabsf(trow[x] - prow[x]);
        if (k & 1) a1 += d; else a0 += d;
    }
    if (lane < 26) {
        int x = lane + 352;
        a1 += fabsf(trow[x] - prow[x]);
    }
    float acc = a0 + a1;
    for (int o = 16; o; o >>= 1) acc += __shfl_xor_sync(0xffffffffu, acc, o);

    __shared__ float ssum[8];
    __shared__ int   sLast;
    const int w = threadIdx.x >> 5;
    if (lane == 0) ssum[w] = acc;
    __syncthreads();
    if (threadIdx.x == 0) {
        float a = 0.f;
#pragma unroll
        for (int k = 0; k < 8; k++) a += ssum[k];
        atomicAdd(&g_abs[blockIdx.x & 31], (double)a);
        __threadfence();
        sLast = (atomicAdd(&g_done_mae, 1u) == (unsigned)(gridDim.x - 1));
        if (sLast) {
            volatile double* ga = g_abs;
            double s = 0.0;
            for (int k = 0; k < 32; k++) s += ga[k];
            out[1] = (float)(s / NTOT_D);
        }
    }
    __syncthreads();
    // ---- last block: reset ALL device state so next graph replay starts
    //      from the same (zero) state as module load ----
    if (sLast) {
        const int t = threadIdx.x;
        if (t < NSHIFT) { g_tp[t] = 0.0; g_zp[t] = 0.0; }
        if (t < NSHIFT * 4) g_win[t] = 0.0;
        if (t < 32) { g_sp[t] = 0.0; g_sp2[t] = 0.0; g_abs[t] = 0.0; }
        if (t == 0) {
            g_idx = 0;
            g_zcount = 0u;
            g_done_zw = 0u;
            g_done_mae = 0u;
        }
    }
}

extern "C" void kernel_launch(void* const* d_in, const int* in_sizes, int n_in,
                              void* d_out, int out_size) {
    const float* pred   = (const float*)d_in[0];
    const float* target = (const float*)d_in[1];
    float* out = (float*)d_out;

    main_kernel<<<MAIN_BLOCKS, 224>>>(pred, target);
    zw_kernel<<<ZW_BLOCKS, 256>>>(pred, out);
    mae_kernel<<<MAE_BLOCKS, 256>>>(pred, target, out);
}

// round 10
// speedup vs baseline: 1.3139x; 1.3139x over previous
#include <cuda_runtime.h>
#include <math.h>

#define BATCH   32
#define H       384
#define KK      378
#define NS      7
#define NSHIFT  49
#define TILE    54
#define PATCH   60
#define NTOT_D  4572288.0

#define STATS_BLOCKS  1568          // 7*7*32
#define ROWS_TOTAL    (BATCH * H)   // 12288
#define ROW_BLOCKS    1756          // ceil(12288 / 7)
#define MAIN_BLOCKS   (STATS_BLOCKS + ROW_BLOCKS)
#define ZB            1184          // zcorr blocks
#define ZGROUPS       (ZB * 4)      // 64-thread groups
#define ZW_BLOCKS     (ZB + 28)
#define MAE_BLOCKS    1512          // 12096 rows / 8 warps

// ---------------- global scratch (no allocations allowed) ----------------
// All zero at module load; the mae last block re-zeroes everything at the end
// of every run so each graph replay starts from identical state.
__device__ double g_tp[NSHIFT];            // dense cross: sum t*p per shift
__device__ double g_zp[NSHIFT];            // sparse cross: sum z*p per shift
__device__ double g_win[NSHIFT * 4];       // windowed sums: t, t^2, m, m*t
__device__ double g_sp[32];                // global sum p (spread slots)
__device__ double g_sp2[32];               // global sum p^2 (spread slots)
__device__ double g_abs[32];               // MAE accumulation (spread slots)
__device__ int    g_idx;
__device__ unsigned int g_zcount;
__device__ unsigned int g_done_zw;
__device__ unsigned int g_done_mae;
__device__ float  g_W[4 * NS * BATCH * H]; // per-row windowed sums [f][v][b][y]
__device__ int    g_zlist[BATCH * H * H];  // worst-case capacity

// ======== fused main kernel: stats blocks + rowsum blocks ========
__global__ __launch_bounds__(224) void main_kernel(
    const float* __restrict__ pred, const float* __restrict__ target)
{
    __shared__ float sT[PATCH * PATCH];
    __shared__ float sP[TILE * TILE];

    const int tid  = threadIdx.x;
    const int lane = tid & 31;
    const int wid  = tid >> 5;

    if (blockIdx.x < STATS_BLOCKS) {
        // ---- dense cross-correlation: warp = v shift, lane = column,
        //      sliding 7-row t window; unroll 7 == window period so the
        //      rotation is absorbed by register renaming (no MOVs). ----
        const int bid = blockIdx.x;
        const int tx = bid % 7;
        const int ty = (bid / 7) % 7;
        const int b  = bid / 49;
        const int x0 = tx * TILE;
        const int y0 = ty * TILE;
        const float* tb = target + (size_t)b * H * H;
        const float* pb = pred   + (size_t)b * H * H;

        for (int k = tid; k < PATCH * PATCH; k += 224) {
            int yy = k / PATCH, xx = k - yy * PATCH;
            sT[k] = tb[(y0 + yy) * H + (x0 + xx)];
        }
        for (int k = tid; k < TILE * TILE; k += 224) {
            int i = k / TILE, j = k - i * TILE;
            sP[k] = pb[(y0 + i + 3) * H + (x0 + j + 3)];
        }
        __syncthreads();

        const int v = wid;                     // this warp's v shift
        const bool two = (lane < TILE - 32);   // lanes 0..21 own a 2nd column
        const int c0 = lane;
        const int c1 = two ? lane + 32 : 0;

        const float* tcol0 = &sT[c0 + v];
        const float* tcol1 = &sT[c1 + v];
        const float* pcol0 = &sP[c0];
        const float* pcol1 = &sP[c1];

        float acc[NS];
#pragma unroll
        for (int u = 0; u < NS; u++) acc[u] = 0.f;

        float ta[NS], tbv[NS];
#pragma unroll
        for (int k = 0; k < 6; k++) {
            ta[k]  = tcol0[k * PATCH];
            tbv[k] = tcol1[k * PATCH];
        }

#pragma unroll 7
        for (int i = 0; i < TILE; i++) {
            ta[6]  = tcol0[(i + 6) * PATCH];
            tbv[6] = tcol1[(i + 6) * PATCH];
            float p0 = pcol0[i * TILE];
            float p1 = two ? pcol1[i * TILE] : 0.f;
#pragma unroll
            for (int u = 0; u < NS; u++) {
                acc[u] = fmaf(ta[u],  p0, acc[u]);
                acc[u] = fmaf(tbv[u], p1, acc[u]);
            }
#pragma unroll
            for (int k = 0; k < 6; k++) { ta[k] = ta[k + 1]; tbv[k] = tbv[k + 1]; }
        }

#pragma unroll
        for (int u = 0; u < NS; u++) {
            float tp = acc[u];
            for (int o = 16; o; o >>= 1)
                tp += __shfl_xor_sync(0xffffffffu, tp, o);
            if (lane == 0)
                atomicAdd(&g_tp[u * NS + v], (double)tp);
        }
    } else {
        // ---- per-row windowed sums + pred sums + z compaction ----
        const int gw = (blockIdx.x - STATS_BLOCKS) * 7 + wid;
        if (gw >= ROWS_TOTAL) return;
        const int b = gw / H;
        const int y = gw - b * H;
        const float* row = target + ((size_t)b * H + y) * H;

        float s0 = 0.f, s1 = 0.f, s2 = 0.f, s3 = 0.f;
        unsigned zm = 0u;
#pragma unroll
        for (int k = 0; k < 12; k++) {
            int x = lane + 32 * k;
            float t = row[x];
            float m = (t > 5.f) ? 1.f : 0.f;
            s0 += t;
            s1  = fmaf(t, t, s1);
            s2 += m;
            s3  = fmaf(m, t, s3);
            if (t <= 5.f) zm |= (1u << k);
        }

        // compact z pixels: one atomic per row
        {
            unsigned cnt = (unsigned)__popc(zm);
            unsigned pre = cnt;
            for (int o = 1; o < 32; o <<= 1) {
                unsigned n = __shfl_up_sync(0xffffffffu, pre, o);
                if (lane >= o) pre += n;
            }
            unsigned tot  = __shfl_sync(0xffffffffu, pre, 31);
            unsigned excl = pre - cnt;
            unsigned base = 0;
            if (tot) {
                if (lane == 31) base = atomicAdd(&g_zcount, tot);
                base = __shfl_sync(0xffffffffu, base, 31);
                unsigned idx = base + excl;
                unsigned mm = zm;
                while (mm) {
                    int k = __ffs(mm) - 1;
                    mm &= mm - 1;
                    g_zlist[idx++] = (b * H + y) * H + lane + 32 * k;
                }
            }
        }

        for (int o = 16; o; o >>= 1) {
            s0 += __shfl_xor_sync(0xffffffffu, s0, o);
            s1 += __shfl_xor_sync(0xffffffffu, s1, o);
            s2 += __shfl_xor_sync(0xffffffffu, s2, o);
            s3 += __shfl_xor_sync(0xffffffffu, s3, o);
        }

        if (lane == 0) {
            float e[12];
#pragma unroll
            for (int k = 0; k < 6; k++) { e[k] = row[k]; e[6 + k] = row[378 + k]; }
#pragma unroll
            for (int v = 0; v < NS; v++) {
                float L0 = 0.f, L1 = 0.f, L2 = 0.f, L3 = 0.f;
                for (int x = 0; x < v; x++) {
                    float t = e[x];
                    float m = (t > 5.f) ? 1.f : 0.f;
                    L0 += t; L1 += t * t; L2 += m; L3 += m * t;
                }
                float R0 = 0.f, R1 = 0.f, R2 = 0.f, R3 = 0.f;
                for (int k = v; k < 6; k++) {
                    float t = e[6 + k];
                    float m = (t > 5.f) ? 1.f : 0.f;
                    R0 += t; R1 += t * t; R2 += m; R3 += m * t;
                }
                g_W[((0 * NS + v) * BATCH + b) * H + y] = s0 - L0 - R0;
                g_W[((1 * NS + v) * BATCH + b) * H + y] = s1 - L1 - R1;
                g_W[((2 * NS + v) * BATCH + b) * H + y] = s2 - L2 - R2;
                g_W[((3 * NS + v) * BATCH + b) * H + y] = s3 - L3 - R3;
            }
        }

        if (y >= 3 && y < 381) {
            const float* prow = pred + ((size_t)b * H + y) * H;
            float sp = 0.f, sp2 = 0.f;
#pragma unroll
            for (int k = 0; k < 12; k++) {
                int x = 3 + lane + 32 * k;
                if (x < 381) {
                    float p = prow[x];
                    sp += p;
                    sp2 = fmaf(p, p, sp2);
                }
            }
            for (int o = 16; o; o >>= 1) {
                sp  += __shfl_xor_sync(0xffffffffu, sp,  o);
                sp2 += __shfl_xor_sync(0xffffffffu, sp2, o);
            }
            if (lane == 0) {
                atomicAdd(&g_sp [gw & 31], (double)sp);
                atomicAdd(&g_sp2[gw & 31], (double)sp2);
            }
        }
    }
}

// ======== fused: zcorr blocks + winsum blocks + last-block argmin ========
__global__ __launch_bounds__(256) void zw_kernel(const float* __restrict__ pred,
                                                 float* out)
{
    __shared__ float  sAcc[64];
    __shared__ double col[H];
    __shared__ double red[256];
    __shared__ double scmse[64];
    __shared__ int    sidx[64];
    __shared__ int    sLast;

    const int tid = threadIdx.x;

    if (blockIdx.x < ZB) {
        // ---- sparse correction: shift-per-thread, 2-deep pipelined loads ----
        if (tid < 64) sAcc[tid] = 0.f;
        __syncthreads();

        const int sid = tid & 63;
        const int u = sid / NS, v = sid - (sid / NS) * NS;
        const bool active = sid < NSHIFT;
        const int grp = (blockIdx.x * 256 + tid) >> 6;
        const int count = (int)g_zcount;

        float acc = 0.f;
        int zi = grp;
        for (; zi + ZGROUPS < count; zi += 2 * ZGROUPS) {
            int code0 = g_zlist[zi];
            int code1 = g_zlist[zi + ZGROUPS];
            int b0 = code0 / (H * H), r0 = code0 - b0 * (H * H);
            int y0 = r0 / H,          x0 = r0 - y0 * H;
            int b1 = code1 / (H * H), r1 = code1 - b1 * (H * H);
            int y1 = r1 / H,          x1 = r1 - y1 * H;
            if (active) {
                int yy0 = y0 - u, xx0 = x0 - v;
                int yy1 = y1 - u, xx1 = x1 - v;
                bool ok0 = (yy0 >= 0 && yy0 < KK && xx0 >= 0 && xx0 < KK);
                bool ok1 = (yy1 >= 0 && yy1 < KK && xx1 >= 0 && xx1 < KK);
                float p0 = ok0 ? pred[(size_t)b0 * H * H + (yy0 + 3) * H + (xx0 + 3)] : 0.f;
                float p1 = ok1 ? pred[(size_t)b1 * H * H + (yy1 + 3) * H + (xx1 + 3)] : 0.f;
                acc += p0 + p1;
            }
        }
        for (; zi < count; zi += ZGROUPS) {
            int code = g_zlist[zi];
            int b = code / (H * H);
            int r = code - b * (H * H);
            int y = r / H;
            int x = r - y * H;
            if (active) {
                int yy = y - u, xx = x - v;
                if (yy >= 0 && yy < KK && xx >= 0 && xx < KK)
                    acc += pred[(size_t)b * H * H + (yy + 3) * H + (xx + 3)];
            }
        }
        if (active && acc != 0.f) atomicAdd(&sAcc[sid], acc);
        __syncthreads();
        if (tid < NSHIFT && sAcc[tid] != 0.f)
            atomicAdd(&g_zp[tid], (double)sAcc[tid]);
    } else {
        // ---- combine per-row windowed sums: block per (f, v) ----
        const int wb = blockIdx.x - ZB;
        const int f = wb / NS;
        const int v = wb - f * NS;
        const float* Wfv = &g_W[((f * NS + v) * BATCH) * H];

        for (int y = tid; y < H; y += 256) {
            double s = 0.0;
#pragma unroll 4
            for (int b = 0; b < BATCH; b++)
                s += (double)Wfv[b * H + y];
            col[y] = s;
        }
        __syncthreads();

        double s = col[tid];
        if (tid + 256 < H) s += col[tid + 256];
        red[tid] = s;
        __syncthreads();
        for (int o = 128; o; o >>= 1) {
            if (tid < o) red[tid] += red[tid + o];
            __syncthreads();
        }
        if (tid < NS) {
            double T = red[0];
            for (int y = 0; y < tid; y++) T -= col[y];
            for (int y = tid + KK; y < H; y++) T -= col[y];
            g_win[(tid * NS + v) * 4 + f] = T;
        }
    }

    // ---- last block performs argmin + cPSNR ----
    __threadfence();
    __syncthreads();
    if (tid == 0)
        sLast = (atomicAdd(&g_done_zw, 1u) == (unsigned)(gridDim.x - 1));
    __syncthreads();
    if (!sLast) return;

    volatile double* vtp  = g_tp;
    volatile double* vzp  = g_zp;
    volatile double* vwin = g_win;
    volatile double* vsp  = g_sp;
    volatile double* vsp2 = g_sp2;

    double Sp = 0.0, Sp2 = 0.0;
    for (int k = 0; k < 32; k++) { Sp += vsp[k]; Sp2 += vsp2[k]; }

    if (tid < 64) {
        double c = 1e300;
        if (tid < NSHIFT) {
            double wt  = vwin[tid * 4 + 0];
            double wt2 = vwin[tid * 4 + 1];
            double n   = vwin[tid * 4 + 2];
            double wmt = vwin[tid * 4 + 3];
            double Sd  = wt - Sp;
            double Sd2 = wt2 - 2.0 * vtp[tid] + Sp2;
            double Sm  = wmt - (Sp - vzp[tid]);
            double bb  = Sm / n;
            c = (Sd2 - 2.0 * bb * Sd + NTOT_D * bb * bb) / n;
        }
        scmse[tid] = c; sidx[tid] = tid;
    }
    __syncthreads();
    for (int o = 32; o; o >>= 1) {
        if (tid < o) {
            if (scmse[tid + o] < scmse[tid]) {
                scmse[tid] = scmse[tid + o];
                sidx[tid]  = sidx[tid + o];
            }
        }
        __syncthreads();
    }
    if (tid == 0) {
        g_idx  = sidx[0];
        out[0] = (float)(-10.0 * log10(scmse[0]));
    }
}

// ======== MAE over winning shift + last-block finalize & self-clean ========
__global__ __launch_bounds__(256) void mae_kernel(
    const float* __restrict__ pred, const float* __restrict__ target, float* out)
{
    const int idx = g_idx;
    const int u = idx / NS, v = idx - (idx / NS) * NS;
    const int gw   = blockIdx.x * 8 + (threadIdx.x >> 5);   // 0 .. 12095
    const int lane = threadIdx.x & 31;
    const int b    = gw / KK;
    const int i    = gw - b * KK;

    const float* prow = pred   + ((size_t)b * H + i + 3) * H + 3;
    const float* trow = target + ((size_t)b * H + i + u) * H + v;

    // fully unrolled: 378 = 32*11 + 26; two accumulators for ILP
    float a0 = 0.f, a1 = 0.f;
#pragma unroll
    for (int k = 0; k < 11; k++) {
        int x = lane + 32 * k;
        float d = fabsf(trow[x] - prow[x]);
        if (k & 1) a1 += d; else a0 += d;
    }
    if (lane < 26) {
        int x = lane + 352;
        a1 += fabsf(trow[x] - prow[x]);
    }
    float acc = a0 + a1;
    for (int o = 16; o; o >>= 1) acc += __shfl_xor_sync(0xffffffffu, acc, o);

    __shared__ float ssum[8];
    __shared__ int   sLast;
    const int w = threadIdx.x >> 5;
    if (lane == 0) ssum[w] = acc;
    __syncthreads();
    if (threadIdx.x == 0) {
        float a = 0.f;
#pragma unroll
        for (int k = 0; k < 8; k++) a += ssum[k];
        atomicAdd(&g_abs[blockIdx.x & 31], (double)a);
        __threadfence();
        sLast = (atomicAdd(&g_done_mae, 1u) == (unsigned)(gridDim.x - 1));
        if (sLast) {
            volatile double* ga = g_abs;
            double s = 0.0;
            for (int k = 0; k < 32; k++) s += ga[k];
            out[1] = (float)(s / NTOT_D);
        }
    }
    __syncthreads();
    // ---- last block: reset ALL device state so next graph replay starts
    //      from the same (zero) state as module load ----
    if (sLast) {
        const int t = threadIdx.x;
        if (t < NSHIFT) { g_tp[t] = 0.0; g_zp[t] = 0.0; }
        if (t < NSHIFT * 4) g_win[t] = 0.0;
        if (t < 32) { g_sp[t] = 0.0; g_sp2[t] = 0.0; g_abs[t] = 0.0; }
        if (t == 0) {
            g_idx = 0;
            g_zcount = 0u;
            g_done_zw = 0u;
            g_done_mae = 0u;
        }
    }
}

extern "C" void kernel_launch(void* const* d_in, const int* in_sizes, int n_in,
                              void* d_out, int out_size) {
    const float* pred   = (const float*)d_in[0];
    const float* target = (const float*)d_in[1];
    float* out = (float*)d_out;

    main_kernel<<<MAIN_BLOCKS, 224>>>(pred, target);
    zw_kernel<<<ZW_BLOCKS, 256>>>(pred, out);
    mae_kernel<<<MAE_BLOCKS, 256>>>(pred, target, out);
}

// round 11
// speedup vs baseline: 1.3221x; 1.0062x over previous
#include <cuda_runtime.h>
#include <math.h>

#define BATCH   32
#define H       384
#define KK      378
#define NS      7
#define NSHIFT  49
#define TILE    54
#define PATCH   60
#define NTOT_D  4572288.0

#define STATS_BLOCKS  1568          // 7*7*32
#define ROWS_TOTAL    (BATCH * H)   // 12288
#define ROW_BLOCKS    1756          // ceil(12288 / 7)
#define MAIN_BLOCKS   (STATS_BLOCKS + ROW_BLOCKS)
#define ZB            1184          // zcorr blocks
#define ZGROUPS       (ZB * 4)      // 64-thread groups
#define ZW_BLOCKS     (ZB + 28)
#define MAE_BLOCKS    1512          // 12096 rows / 8 warps

// ---------------- global scratch (no allocations allowed) ----------------
// All zero at module load; the mae last block re-zeroes everything at the end
// of every run so each graph replay starts from identical state.
__device__ double g_tp[NSHIFT];            // dense cross: sum t*p per shift
__device__ double g_zp[NSHIFT];            // sparse cross: sum z*p per shift
__device__ double g_win[NSHIFT * 4];       // windowed sums: t, t^2, m, m*t
__device__ double g_sp[32];                // global sum p (spread slots)
__device__ double g_sp2[32];               // global sum p^2 (spread slots)
__device__ double g_abs[32];               // MAE accumulation (spread slots)
__device__ int    g_idx;
__device__ unsigned int g_zcount;
__device__ unsigned int g_done_zw;
__device__ unsigned int g_done_mae;
__device__ float  g_W[4 * NS * BATCH * H]; // per-row windowed sums [f][v][b][y]
__device__ int    g_zlist[BATCH * H * H];  // worst-case capacity

// ======== fused main kernel: stats blocks + rowsum blocks ========
// launch_bounds(224, 4): raise the per-thread register budget (~72) so ptxas
// can software-pipeline the LDS->FFMA stream instead of stalling at regs=32.
__global__ __launch_bounds__(224, 4) void main_kernel(
    const float* __restrict__ pred, const float* __restrict__ target)
{
    __shared__ float sT[PATCH * PATCH];
    __shared__ float sP[TILE * TILE];

    const int tid  = threadIdx.x;
    const int lane = tid & 31;
    const int wid  = tid >> 5;

    if (blockIdx.x < STATS_BLOCKS) {
        // ---- dense cross-correlation: warp = v shift, lane = column,
        //      sliding 7-row t window (unroll 7 = window period) with
        //      explicit one-iteration load prefetch. ----
        const int bid = blockIdx.x;
        const int tx = bid % 7;
        const int ty = (bid / 7) % 7;
        const int b  = bid / 49;
        const int x0 = tx * TILE;
        const int y0 = ty * TILE;
        const float* tb = target + (size_t)b * H * H;
        const float* pb = pred   + (size_t)b * H * H;

        // stage: warp-per-row, coalesced, no div/mod, full MLP
        for (int r = wid; r < PATCH; r += 7) {
            const float* src = tb + (y0 + r) * H + x0;
            if (lane < 30) {
                sT[r * PATCH + lane]      = src[lane];
                sT[r * PATCH + lane + 30] = src[lane + 30];
            }
        }
        for (int r = wid; r < TILE; r += 7) {
            const float* src = pb + (y0 + r + 3) * H + (x0 + 3);
            if (lane < 27) {
                sP[r * TILE + lane]      = src[lane];
                sP[r * TILE + lane + 27] = src[lane + 27];
            }
        }
        __syncthreads();

        const int v = wid;                     // this warp's v shift
        const bool two = (lane < TILE - 32);   // lanes 0..21 own a 2nd column
        const int c0 = lane;
        const int c1 = two ? lane + 32 : 0;

        const float* tcol0 = &sT[c0 + v];
        const float* tcol1 = &sT[c1 + v];
        const float* pcol0 = &sP[c0];
        const float* pcol1 = &sP[c1];

        float acc[NS];
#pragma unroll
        for (int u = 0; u < NS; u++) acc[u] = 0.f;

        float ta[NS], tbv[NS];
#pragma unroll
        for (int k = 0; k < 6; k++) {
            ta[k]  = tcol0[k * PATCH];
            tbv[k] = tcol1[k * PATCH];
        }

        // prefetch registers for iteration 0
        float nta = tcol0[6 * PATCH];
        float ntb = tcol1[6 * PATCH];
        float np0 = pcol0[0];
        float np1 = two ? pcol1[0] : 0.f;

#pragma unroll 7
        for (int i = 0; i < TILE; i++) {
            ta[6]  = nta;
            tbv[6] = ntb;
            float p0 = np0;
            float p1 = np1;
            if (i + 1 < TILE) {
                nta = tcol0[(i + 7) * PATCH];
                ntb = tcol1[(i + 7) * PATCH];
                np0 = pcol0[(i + 1) * TILE];
                np1 = two ? pcol1[(i + 1) * TILE] : 0.f;
            }
#pragma unroll
            for (int u = 0; u < NS; u++) {
                acc[u] = fmaf(ta[u],  p0, acc[u]);
                acc[u] = fmaf(tbv[u], p1, acc[u]);
            }
#pragma unroll
            for (int k = 0; k < 6; k++) { ta[k] = ta[k + 1]; tbv[k] = tbv[k + 1]; }
        }

#pragma unroll
        for (int u = 0; u < NS; u++) {
            float tp = acc[u];
            for (int o = 16; o; o >>= 1)
                tp += __shfl_xor_sync(0xffffffffu, tp, o);
            if (lane == 0)
                atomicAdd(&g_tp[u * NS + v], (double)tp);
        }
    } else {
        // ---- per-row windowed sums + pred sums + z compaction ----
        const int gw = (blockIdx.x - STATS_BLOCKS) * 7 + wid;
        if (gw >= ROWS_TOTAL) return;
        const int b = gw / H;
        const int y = gw - b * H;
        const float* row = target + ((size_t)b * H + y) * H;

        float s0 = 0.f, s1 = 0.f, s2 = 0.f, s3 = 0.f;
        unsigned zm = 0u;
#pragma unroll
        for (int k = 0; k < 12; k++) {
            int x = lane + 32 * k;
            float t = row[x];
            float m = (t > 5.f) ? 1.f : 0.f;
            s0 += t;
            s1  = fmaf(t, t, s1);
            s2 += m;
            s3  = fmaf(m, t, s3);
            if (t <= 5.f) zm |= (1u << k);
        }

        // compact z pixels: one atomic per row
        {
            unsigned cnt = (unsigned)__popc(zm);
            unsigned pre = cnt;
            for (int o = 1; o < 32; o <<= 1) {
                unsigned n = __shfl_up_sync(0xffffffffu, pre, o);
                if (lane >= o) pre += n;
            }
            unsigned tot  = __shfl_sync(0xffffffffu, pre, 31);
            unsigned excl = pre - cnt;
            unsigned base = 0;
            if (tot) {
                if (lane == 31) base = atomicAdd(&g_zcount, tot);
                base = __shfl_sync(0xffffffffu, base, 31);
                unsigned idx = base + excl;
                unsigned mm = zm;
                while (mm) {
                    int k = __ffs(mm) - 1;
                    mm &= mm - 1;
                    g_zlist[idx++] = (b * H + y) * H + lane + 32 * k;
                }
            }
        }

        for (int o = 16; o; o >>= 1) {
            s0 += __shfl_xor_sync(0xffffffffu, s0, o);
            s1 += __shfl_xor_sync(0xffffffffu, s1, o);
            s2 += __shfl_xor_sync(0xffffffffu, s2, o);
            s3 += __shfl_xor_sync(0xffffffffu, s3, o);
        }

        if (lane == 0) {
            float e[12];
#pragma unroll
            for (int k = 0; k < 6; k++) { e[k] = row[k]; e[6 + k] = row[378 + k]; }
#pragma unroll
            for (int v = 0; v < NS; v++) {
                float L0 = 0.f, L1 = 0.f, L2 = 0.f, L3 = 0.f;
                for (int x = 0; x < v; x++) {
                    float t = e[x];
                    float m = (t > 5.f) ? 1.f : 0.f;
                    L0 += t; L1 += t * t; L2 += m; L3 += m * t;
                }
                float R0 = 0.f, R1 = 0.f, R2 = 0.f, R3 = 0.f;
                for (int k = v; k < 6; k++) {
                    float t = e[6 + k];
                    float m = (t > 5.f) ? 1.f : 0.f;
                    R0 += t; R1 += t * t; R2 += m; R3 += m * t;
                }
                g_W[((0 * NS + v) * BATCH + b) * H + y] = s0 - L0 - R0;
                g_W[((1 * NS + v) * BATCH + b) * H + y] = s1 - L1 - R1;
                g_W[((2 * NS + v) * BATCH + b) * H + y] = s2 - L2 - R2;
                g_W[((3 * NS + v) * BATCH + b) * H + y] = s3 - L3 - R3;
            }
        }

        if (y >= 3 && y < 381) {
            const float* prow = pred + ((size_t)b * H + y) * H;
            float sp = 0.f, sp2 = 0.f;
#pragma unroll
            for (int k = 0; k < 12; k++) {
                int x = 3 + lane + 32 * k;
                if (x < 381) {
                    float p = prow[x];
                    sp += p;
                    sp2 = fmaf(p, p, sp2);
                }
            }
            for (int o = 16; o; o >>= 1) {
                sp  += __shfl_xor_sync(0xffffffffu, sp,  o);
                sp2 += __shfl_xor_sync(0xffffffffu, sp2, o);
            }
            if (lane == 0) {
                atomicAdd(&g_sp [gw & 31], (double)sp);
                atomicAdd(&g_sp2[gw & 31], (double)sp2);
            }
        }
    }
}

// ======== fused: zcorr blocks + winsum blocks + last-block argmin ========
__global__ __launch_bounds__(256) void zw_kernel(const float* __restrict__ pred,
                                                 float* out)
{
    __shared__ float  sAcc[64];
    __shared__ double col[H];
    __shared__ double red[256];
    __shared__ double scmse[64];
    __shared__ int    sidx[64];
    __shared__ int    sLast;

    const int tid = threadIdx.x;

    if (blockIdx.x < ZB) {
        // ---- sparse correction: shift-per-thread, 2-deep pipelined loads ----
        if (tid < 64) sAcc[tid] = 0.f;
        __syncthreads();

        const int sid = tid & 63;
        const int u = sid / NS, v = sid - (sid / NS) * NS;
        const bool active = sid < NSHIFT;
        const int grp = (blockIdx.x * 256 + tid) >> 6;
        const int count = (int)g_zcount;

        float acc = 0.f;
        int zi = grp;
        for (; zi + ZGROUPS < count; zi += 2 * ZGROUPS) {
            int code0 = g_zlist[zi];
            int code1 = g_zlist[zi + ZGROUPS];
            int b0 = code0 / (H * H), r0 = code0 - b0 * (H * H);
            int y0 = r0 / H,          x0 = r0 - y0 * H;
            int b1 = code1 / (H * H), r1 = code1 - b1 * (H * H);
            int y1 = r1 / H,          x1 = r1 - y1 * H;
            if (active) {
                int yy0 = y0 - u, xx0 = x0 - v;
                int yy1 = y1 - u, xx1 = x1 - v;
                bool ok0 = (yy0 >= 0 && yy0 < KK && xx0 >= 0 && xx0 < KK);
                bool ok1 = (yy1 >= 0 && yy1 < KK && xx1 >= 0 && xx1 < KK);
                float p0 = ok0 ? pred[(size_t)b0 * H * H + (yy0 + 3) * H + (xx0 + 3)] : 0.f;
                float p1 = ok1 ? pred[(size_t)b1 * H * H + (yy1 + 3) * H + (xx1 + 3)] : 0.f;
                acc += p0 + p1;
            }
        }
        for (; zi < count; zi += ZGROUPS) {
            int code = g_zlist[zi];
            int b = code / (H * H);
            int r = code - b * (H * H);
            int y = r / H;
            int x = r - y * H;
            if (active) {
                int yy = y - u, xx = x - v;
                if (yy >= 0 && yy < KK && xx >= 0 && xx < KK)
                    acc += pred[(size_t)b * H * H + (yy + 3) * H + (xx + 3)];
            }
        }
        if (active && acc != 0.f) atomicAdd(&sAcc[sid], acc);
        __syncthreads();
        if (tid < NSHIFT && sAcc[tid] != 0.f)
            atomicAdd(&g_zp[tid], (double)sAcc[tid]);
    } else {
        // ---- combine per-row windowed sums: block per (f, v) ----
        const int wb = blockIdx.x - ZB;
        const int f = wb / NS;
        const int v = wb - f * NS;
        const float* Wfv = &g_W[((f * NS + v) * BATCH) * H];

        for (int y = tid; y < H; y += 256) {
            double s = 0.0;
#pragma unroll 4
            for (int b = 0; b < BATCH; b++)
                s += (double)Wfv[b * H + y];
            col[y] = s;
        }
        __syncthreads();

        double s = col[tid];
        if (tid + 256 < H) s += col[tid + 256];
        red[tid] = s;
        __syncthreads();
        for (int o = 128; o; o >>= 1) {
            if (tid < o) red[tid] += red[tid + o];
            __syncthreads();
        }
        if (tid < NS) {
            double T = red[0];
            for (int y = 0; y < tid; y++) T -= col[y];
            for (int y = tid + KK; y < H; y++) T -= col[y];
            g_win[(tid * NS + v) * 4 + f] = T;
        }
    }

    // ---- last block performs argmin + cPSNR ----
    __threadfence();
    __syncthreads();
    if (tid == 0)
        sLast = (atomicAdd(&g_done_zw, 1u) == (unsigned)(gridDim.x - 1));
    __syncthreads();
    if (!sLast) return;

    volatile double* vtp  = g_tp;
    volatile double* vzp  = g_zp;
    volatile double* vwin = g_win;
    volatile double* vsp  = g_sp;
    volatile double* vsp2 = g_sp2;

    double Sp = 0.0, Sp2 = 0.0;
    for (int k = 0; k < 32; k++) { Sp += vsp[k]; Sp2 += vsp2[k]; }

    if (tid < 64) {
        double c = 1e300;
        if (tid < NSHIFT) {
            double wt  = vwin[tid * 4 + 0];
            double wt2 = vwin[tid * 4 + 1];
            double n   = vwin[tid * 4 + 2];
            double wmt = vwin[tid * 4 + 3];
            double Sd  = wt - Sp;
            double Sd2 = wt2 - 2.0 * vtp[tid] + Sp2;
            double Sm  = wmt - (Sp - vzp[tid]);
            double bb  = Sm / n;
            c = (Sd2 - 2.0 * bb * Sd + NTOT_D * bb * bb) / n;
        }
        scmse[tid] = c; sidx[tid] = tid;
    }
    __syncthreads();
    for (int o = 32; o; o >>= 1) {
        if (tid < o) {
            if (scmse[tid + o] < scmse[tid]) {
                scmse[tid] = scmse[tid + o];
                sidx[tid]  = sidx[tid + o];
            }
        }
        __syncthreads();
    }
    if (tid == 0) {
        g_idx  = sidx[0];
        out[0] = (float)(-10.0 * log10(scmse[0]));
    }
}

// ======== MAE over winning shift + last-block finalize & self-clean ========
__global__ __launch_bounds__(256) void mae_kernel(
    const float* __restrict__ pred, const float* __restrict__ target, float* out)
{
    const int idx = g_idx;
    const int u = idx / NS, v = idx - (idx / NS) * NS;
    const int gw   = blockIdx.x * 8 + (threadIdx.x >> 5);   // 0 .. 12095
    const int lane = threadIdx.x & 31;
    const int b    = gw / KK;
    const int i    = gw - b * KK;

    const float* prow = pred   + ((size_t)b * H + i + 3) * H + 3;
    const float* trow = target + ((size_t)b * H + i + u) * H + v;

    // fully unrolled: 378 = 32*11 + 26; two accumulators for ILP
    float a0 = 0.f, a1 = 0.f;
#pragma unroll
    for (int k = 0; k < 11; k++) {
        int x = lane + 32 * k;
        float d = fabsf(trow[x] - prow[x]);
        if (k & 1) a1 += d; else a0 += d;
    }
    if (lane < 26) {
        int x = lane + 352;
        a1 += fabsf(trow[x] - prow[x]);
    }
    float acc = a0 + a1;
    for (int o = 16; o; o >>= 1) acc += __shfl_xor_sync(0xffffffffu, acc, o);

    __shared__ float ssum[8];
    __shared__ int   sLast;
    const int w = threadIdx.x >> 5;
    if (lane == 0) ssum[w] = acc;
    __syncthreads();
    if (threadIdx.x == 0) {
        float a = 0.f;
#pragma unroll
        for (int k = 0; k < 8; k++) a += ssum[k];
        atomicAdd(&g_abs[blockIdx.x & 31], (double)a);
        __threadfence();
        sLast = (atomicAdd(&g_done_mae, 1u) == (unsigned)(gridDim.x - 1));
        if (sLast) {
            volatile double* ga = g_abs;
            double s = 0.0;
            for (int k = 0; k < 32; k++) s += ga[k];
            out[1] = (float)(s / NTOT_D);
        }
    }
    __syncthreads();
    // ---- last block: reset ALL device state so next graph replay starts
    //      from the same (zero) state as module load ----
    if (sLast) {
        const int t = threadIdx.x;
        if (t < NSHIFT) { g_tp[t] = 0.0; g_zp[t] = 0.0; }
        if (t < NSHIFT * 4) g_win[t] = 0.0;
        if (t < 32) { g_sp[t] = 0.0; g_sp2[t] = 0.0; g_abs[t] = 0.0; }
        if (t == 0) {
            g_idx = 0;
            g_zcount = 0u;
            g_done_zw = 0u;
            g_done_mae = 0u;
        }
    }
}

extern "C" void kernel_launch(void* const* d_in, const int* in_sizes, int n_in,
                              void* d_out, int out_size) {
    const float* pred   = (const float*)d_in[0];
    const float* target = (const float*)d_in[1];
    float* out = (float*)d_out;

    main_kernel<<<MAIN_BLOCKS, 224>>>(pred, target);
    zw_kernel<<<ZW_BLOCKS, 256>>>(pred, out);
    mae_kernel<<<MAE_BLOCKS, 256>>>(pred, target, out);
}

// round 13
// speedup vs baseline: 1.3636x; 1.0314x over previous
#include <cuda_runtime.h>
#include <math.h>

#define BATCH   32
#define H       384
#define KK      378
#define NS      7
#define NSHIFT  49
#define TILE    54
#define NTOT_D  4572288.0

// stats x-tiles: widths 64,64,64,64,64,58 (starts 0,64,...,320)
#define XT      6
#define STATS_BLOCKS  (XT * 7 * BATCH)          // 1344
#define ROWS_TOTAL    (BATCH * H)               // 12288
#define ROW_BLOCKS    1756                      // ceil(12288 / 7)
#define MAIN_BLOCKS   (STATS_BLOCKS + ROW_BLOCKS)
#define ZB            1184
#define ZGROUPS       (ZB * 4)
#define ZW_BLOCKS     (ZB + 28)
#define MAE_BLOCKS    1512

#define ST_W    72          // sT row stride (floats), padded
#define SP_W    64          // sP row stride (floats)

// ---------------- global scratch (no allocations allowed) ----------------
// All zero at module load; the mae last block re-zeroes everything at the end
// of every run so each graph replay starts from identical state.
__device__ double g_tp[NSHIFT];
__device__ double g_zp[NSHIFT];
__device__ double g_win[NSHIFT * 4];
__device__ double g_sp[32];
__device__ double g_sp2[32];
__device__ double g_abs[32];
__device__ int    g_idx;
__device__ unsigned int g_zcount;
__device__ unsigned int g_done_zw;
__device__ unsigned int g_done_mae;
__device__ float  g_W[4 * NS * BATCH * H];
__device__ int    g_zlist[BATCH * H * H];

// stats inner loop: sliding 7-row window, float2 loads, parity-specialized.
template <bool ODD>
__device__ __forceinline__ void corr_columns(
    const float* sT, const float* sP, int e, int j0, float* acc)
{
    const float2* tb0 = reinterpret_cast<const float2*>(sT + e);
    const float2* tb1 = tb0 + 1;                      // only used when ODD
    const float2* pbs = reinterpret_cast<const float2*>(sP + j0);

    float wa[NS], wb[NS];
#pragma unroll
    for (int k = 0; k < 6; k++) {
        if (ODD) {
            wa[k] = tb0[k * (ST_W / 2)].y;
            wb[k] = tb1[k * (ST_W / 2)].x;
        } else {
            float2 q = tb0[k * (ST_W / 2)];
            wa[k] = q.x; wb[k] = q.y;
        }
    }
    float2 qa = tb0[6 * (ST_W / 2)];
    float2 qb = ODD ? tb1[6 * (ST_W / 2)] : qa;

#pragma unroll 7
    for (int i = 0; i < TILE; i++) {
        if (ODD) { wa[6] = qa.y; wb[6] = qb.x; }
        else     { wa[6] = qa.x; wb[6] = qa.y; }
        float2 pp = pbs[i * (SP_W / 2)];
        if (i + 1 < TILE) {
            qa = tb0[(i + 7) * (ST_W / 2)];
            if (ODD) qb = tb1[(i + 7) * (ST_W / 2)];
        }
#pragma unroll
        for (int u = 0; u < NS; u++) {
            acc[u] = fmaf(wa[u], pp.x, acc[u]);
            acc[u] = fmaf(wb[u], pp.y, acc[u]);
        }
#pragma unroll
        for (int k = 0; k < 6; k++) { wa[k] = wa[k + 1]; wb[k] = wb[k + 1]; }
    }
}

// ======== fused main kernel: stats blocks + rowsum blocks ========
__global__ __launch_bounds__(224, 4) void main_kernel(
    const float* __restrict__ pred, const float* __restrict__ target)
{
    __shared__ float sT[60 * ST_W];
    __shared__ float sP[TILE * SP_W];

    const int tid  = threadIdx.x;
    const int lane = tid & 31;
    const int wid  = tid >> 5;

    if (blockIdx.x < STATS_BLOCKS) {
        // ---- dense cross-correlation: warp = v shift, lane = 2 adjacent cols
        const int bid = blockIdx.x;
        const int tx = bid % XT;
        const int ty = (bid / XT) % 7;
        const int b  = bid / (XT * 7);
        const int x0 = tx * 64;
        const int Wd = (tx == XT - 1) ? 58 : 64;   // output cols this tile
        const int y0 = ty * TILE;
        const float* tb = target + (size_t)b * H * H;
        const float* pb = pred   + (size_t)b * H * H;

        // stage target patch rows [y0, y0+60) cols [x0, x0+Wd+6)  (<= 70 cols)
        for (int r = wid; r < 60; r += 7) {
            const float* src = tb + (y0 + r) * H + x0;
            float* dst = &sT[r * ST_W];
            if (lane < Wd + 6) dst[lane] = src[lane];
            int c2 = lane + 32;
            if (c2 < Wd + 6) dst[c2] = src[c2];
            int c3 = lane + 64;                 // FIX: cols 64..69 were unstaged
            if (c3 < Wd + 6) dst[c3] = src[c3];
        }
        // stage pred tile rows [y0+3, y0+57) cols [x0+3, x0+3+Wd)
        for (int r = wid; r < TILE; r += 7) {
            const float* src = pb + (y0 + r + 3) * H + (x0 + 3);
            float* dst = &sP[r * SP_W];
            if (lane < Wd) dst[lane] = src[lane];
            int c2 = lane + 32;
            if (c2 < Wd) dst[c2] = src[c2];
        }
        __syncthreads();

        const int v  = wid;           // this warp's v shift
        const int j0 = 2 * lane;      // this lane's pred columns j0, j0+1

        float acc[NS];
#pragma unroll
        for (int u = 0; u < NS; u++) acc[u] = 0.f;

        if (j0 < Wd) {
            const int e = (j0 + v) & ~1;   // even float2 base in sT row
            if (v & 1) corr_columns<true >(sT, sP, e, j0, acc);
            else       corr_columns<false>(sT, sP, e, j0, acc);
        }

#pragma unroll
        for (int u = 0; u < NS; u++) {
            float tp = acc[u];
            for (int o = 16; o; o >>= 1)
                tp += __shfl_xor_sync(0xffffffffu, tp, o);
            if (lane == 0)
                atomicAdd(&g_tp[u * NS + v], (double)tp);
        }
    } else {
        // ---- per-row windowed sums + pred sums + z compaction ----
        const int gw = (blockIdx.x - STATS_BLOCKS) * 7 + wid;
        if (gw >= ROWS_TOTAL) return;
        const int b = gw / H;
        const int y = gw - b * H;
        const float* row = target + ((size_t)b * H + y) * H;

        float s0 = 0.f, s1 = 0.f, s2 = 0.f, s3 = 0.f;
        unsigned zm = 0u;
#pragma unroll
        for (int k = 0; k < 12; k++) {
            int x = lane + 32 * k;
            float t = row[x];
            float m = (t > 5.f) ? 1.f : 0.f;
            s0 += t;
            s1  = fmaf(t, t, s1);
            s2 += m;
            s3  = fmaf(m, t, s3);
            if (t <= 5.f) zm |= (1u << k);
        }

        // compact z pixels: one atomic per row
        {
            unsigned cnt = (unsigned)__popc(zm);
            unsigned pre = cnt;
            for (int o = 1; o < 32; o <<= 1) {
                unsigned n = __shfl_up_sync(0xffffffffu, pre, o);
                if (lane >= o) pre += n;
            }
            unsigned tot  = __shfl_sync(0xffffffffu, pre, 31);
            unsigned excl = pre - cnt;
            unsigned base = 0;
            if (tot) {
                if (lane == 31) base = atomicAdd(&g_zcount, tot);
                base = __shfl_sync(0xffffffffu, base, 31);
                unsigned idx = base + excl;
                unsigned mm = zm;
                while (mm) {
                    int k = __ffs(mm) - 1;
                    mm &= mm - 1;
                    g_zlist[idx++] = (b * H + y) * H + lane + 32 * k;
                }
            }
        }

        for (int o = 16; o; o >>= 1) {
            s0 += __shfl_xor_sync(0xffffffffu, s0, o);
            s1 += __shfl_xor_sync(0xffffffffu, s1, o);
            s2 += __shfl_xor_sync(0xffffffffu, s2, o);
            s3 += __shfl_xor_sync(0xffffffffu, s3, o);
        }

        if (lane == 0) {
            float e[12];
#pragma unroll
            for (int k = 0; k < 6; k++) { e[k] = row[k]; e[6 + k] = row[378 + k]; }
#pragma unroll
            for (int v = 0; v < NS; v++) {
                float L0 = 0.f, L1 = 0.f, L2 = 0.f, L3 = 0.f;
                for (int x = 0; x < v; x++) {
                    float t = e[x];
                    float m = (t > 5.f) ? 1.f : 0.f;
                    L0 += t; L1 += t * t; L2 += m; L3 += m * t;
                }
                float R0 = 0.f, R1 = 0.f, R2 = 0.f, R3 = 0.f;
                for (int k = v; k < 6; k++) {
                    float t = e[6 + k];
                    float m = (t > 5.f) ? 1.f : 0.f;
                    R0 += t; R1 += t * t; R2 += m; R3 += m * t;
                }
                g_W[((0 * NS + v) * BATCH + b) * H + y] = s0 - L0 - R0;
                g_W[((1 * NS + v) * BATCH + b) * H + y] = s1 - L1 - R1;
                g_W[((2 * NS + v) * BATCH + b) * H + y] = s2 - L2 - R2;
                g_W[((3 * NS + v) * BATCH + b) * H + y] = s3 - L3 - R3;
            }
        }

        if (y >= 3 && y < 381) {
            const float* prow = pred + ((size_t)b * H + y) * H;
            float sp = 0.f, sp2 = 0.f;
#pragma unroll
            for (int k = 0; k < 12; k++) {
                int x = 3 + lane + 32 * k;
                if (x < 381) {
                    float p = prow[x];
                    sp += p;
                    sp2 = fmaf(p, p, sp2);
                }
            }
            for (int o = 16; o; o >>= 1) {
                sp  += __shfl_xor_sync(0xffffffffu, sp,  o);
                sp2 += __shfl_xor_sync(0xffffffffu, sp2, o);
            }
            if (lane == 0) {
                atomicAdd(&g_sp [gw & 31], (double)sp);
                atomicAdd(&g_sp2[gw & 31], (double)sp2);
            }
        }
    }
}

// ======== fused: zcorr blocks + winsum blocks + last-block argmin ========
__global__ __launch_bounds__(256) void zw_kernel(const float* __restrict__ pred,
                                                 float* out)
{
    __shared__ float  sAcc[64];
    __shared__ double col[H];
    __shared__ double red[256];
    __shared__ double scmse[64];
    __shared__ int    sidx[64];
    __shared__ int    sLast;

    const int tid = threadIdx.x;

    if (blockIdx.x < ZB) {
        if (tid < 64) sAcc[tid] = 0.f;
        __syncthreads();

        const int sid = tid & 63;
        const int u = sid / NS, v = sid - (sid / NS) * NS;
        const bool active = sid < NSHIFT;
        const int grp = (blockIdx.x * 256 + tid) >> 6;
        const int count = (int)g_zcount;

        float acc = 0.f;
        int zi = grp;
        for (; zi + ZGROUPS < count; zi += 2 * ZGROUPS) {
            int code0 = g_zlist[zi];
            int code1 = g_zlist[zi + ZGROUPS];
            int b0 = code0 / (H * H), r0 = code0 - b0 * (H * H);
            int y0 = r0 / H,          x0 = r0 - y0 * H;
            int b1 = code1 / (H * H), r1 = code1 - b1 * (H * H);
            int y1 = r1 / H,          x1 = r1 - y1 * H;
            if (active) {
                int yy0 = y0 - u, xx0 = x0 - v;
                int yy1 = y1 - u, xx1 = x1 - v;
                bool ok0 = (yy0 >= 0 && yy0 < KK && xx0 >= 0 && xx0 < KK);
                bool ok1 = (yy1 >= 0 && yy1 < KK && xx1 >= 0 && xx1 < KK);
                float p0 = ok0 ? pred[(size_t)b0 * H * H + (yy0 + 3) * H + (xx0 + 3)] : 0.f;
                float p1 = ok1 ? pred[(size_t)b1 * H * H + (yy1 + 3) * H + (xx1 + 3)] : 0.f;
                acc += p0 + p1;
            }
        }
        for (; zi < count; zi += ZGROUPS) {
            int code = g_zlist[zi];
            int b = code / (H * H);
            int r = code - b * (H * H);
            int y = r / H;
            int x = r - y * H;
            if (active) {
                int yy = y - u, xx = x - v;
                if (yy >= 0 && yy < KK && xx >= 0 && xx < KK)
                    acc += pred[(size_t)b * H * H + (yy + 3) * H + (xx + 3)];
            }
        }
        if (active && acc != 0.f) atomicAdd(&sAcc[sid], acc);
        __syncthreads();
        if (tid < NSHIFT && sAcc[tid] != 0.f)
            atomicAdd(&g_zp[tid], (double)sAcc[tid]);
    } else {
        const int wb = blockIdx.x - ZB;
        const int f = wb / NS;
        const int v = wb - f * NS;
        const float* Wfv = &g_W[((f * NS + v) * BATCH) * H];

        for (int y = tid; y < H; y += 256) {
            double s = 0.0;
#pragma unroll 4
            for (int b = 0; b < BATCH; b++)
                s += (double)Wfv[b * H + y];
            col[y] = s;
        }
        __syncthreads();

        double s = col[tid];
        if (tid + 256 < H) s += col[tid + 256];
        red[tid] = s;
        __syncthreads();
        for (int o = 128; o; o >>= 1) {
            if (tid < o) red[tid] += red[tid + o];
            __syncthreads();
        }
        if (tid < NS) {
            double T = red[0];
            for (int y = 0; y < tid; y++) T -= col[y];
            for (int y = tid + KK; y < H; y++) T -= col[y];
            g_win[(tid * NS + v) * 4 + f] = T;
        }
    }

    __threadfence();
    __syncthreads();
    if (tid == 0)
        sLast = (atomicAdd(&g_done_zw, 1u) == (unsigned)(gridDim.x - 1));
    __syncthreads();
    if (!sLast) return;

    volatile double* vtp  = g_tp;
    volatile double* vzp  = g_zp;
    volatile double* vwin = g_win;
    volatile double* vsp  = g_sp;
    volatile double* vsp2 = g_sp2;

    double Sp = 0.0, Sp2 = 0.0;
    for (int k = 0; k < 32; k++) { Sp += vsp[k]; Sp2 += vsp2[k]; }

    if (tid < 64) {
        double c = 1e300;
        if (tid < NSHIFT) {
            double wt  = vwin[tid * 4 + 0];
            double wt2 = vwin[tid * 4 + 1];
            double n   = vwin[tid * 4 + 2];
            double wmt = vwin[tid * 4 + 3];
            double Sd  = wt - Sp;
            double Sd2 = wt2 - 2.0 * vtp[tid] + Sp2;
            double Sm  = wmt - (Sp - vzp[tid]);
            double bb  = Sm / n;
            c = (Sd2 - 2.0 * bb * Sd + NTOT_D * bb * bb) / n;
        }
        scmse[tid] = c; sidx[tid] = tid;
    }
    __syncthreads();
    for (int o = 32; o; o >>= 1) {
        if (tid < o) {
            if (scmse[tid + o] < scmse[tid]) {
                scmse[tid] = scmse[tid + o];
                sidx[tid]  = sidx[tid + o];
            }
        }
        __syncthreads();
    }
    if (tid == 0) {
        g_idx  = sidx[0];
        out[0] = (float)(-10.0 * log10(scmse[0]));
    }
}

// ======== MAE over winning shift + last-block finalize & self-clean ========
__global__ __launch_bounds__(256) void mae_kernel(
    const float* __restrict__ pred, const float* __restrict__ target, float* out)
{
    const int idx = g_idx;
    const int u = idx / NS, v = idx - (idx / NS) * NS;
    const int gw   = blockIdx.x * 8 + (threadIdx.x >> 5);
    const int lane = threadIdx.x & 31;
    const int b    = gw / KK;
    const int i    = gw - b * KK;

    const float* prow = pred   + ((size_t)b * H + i + 3) * H + 3;
    const float* trow = target + ((size_t)b * H + i + u) * H + v;

    float a0 = 0.f, a1 = 0.f;
#pragma unroll
    for (int k = 0; k < 11; k++) {
        int x = lane + 32 * k;
        float d = fabsf(trow[x] - prow[x]);
        if (k & 1) a1 += d; else a0 += d;
    }
    if (lane < 26) {
        int x = lane + 352;
        a1 += fabsf(trow[x] - prow[x]);
    }
    float acc = a0 + a1;
    for (int o = 16; o; o >>= 1) acc += __shfl_xor_sync(0xffffffffu, acc, o);

    __shared__ float ssum[8];
    __shared__ int   sLast;
    const int w = threadIdx.x >> 5;
    if (lane == 0) ssum[w] = acc;
    __syncthreads();
    if (threadIdx.x == 0) {
        float a = 0.f;
#pragma unroll
        for (int k = 0; k < 8; k++) a += ssum[k];
        atomicAdd(&g_abs[blockIdx.x & 31], (double)a);
        __threadfence();
        sLast = (atomicAdd(&g_done_mae, 1u) == (unsigned)(gridDim.x - 1));
        if (sLast) {
            volatile double* ga = g_abs;
            double s = 0.0;
            for (int k = 0; k < 32; k++) s += ga[k];
            out[1] = (float)(s / NTOT_D);
        }
    }
    __syncthreads();
    if (sLast) {
        const int t = threadIdx.x;
        if (t < NSHIFT) { g_tp[t] = 0.0; g_zp[t] = 0.0; }
        if (t < NSHIFT * 4) g_win[t] = 0.0;
        if (t < 32) { g_sp[t] = 0.0; g_sp2[t] = 0.0; g_abs[t] = 0.0; }
        if (t == 0) {
            g_idx = 0;
            g_zcount = 0u;
            g_done_zw = 0u;
            g_done_mae = 0u;
        }
    }
}

extern "C" void kernel_launch(void* const* d_in, const int* in_sizes, int n_in,
                              void* d_out, int out_size) {
    const float* pred   = (const float*)d_in[0];
    const float* target = (const float*)d_in[1];
    float* out = (float*)d_out;

    main_kernel<<<MAIN_BLOCKS, 224>>>(pred, target);
    zw_kernel<<<ZW_BLOCKS, 256>>>(pred, out);
    mae_kernel<<<MAE_BLOCKS, 256>>>(pred, target, out);
}

// round 14
// speedup vs baseline: 1.4123x; 1.0357x over previous
#include <cuda_runtime.h>
#include <math.h>

#define BATCH   32
#define H       384
#define KK      378
#define NS      7
#define NSHIFT  49
#define TILE    54
#define NTOT_D  4572288.0

// stats x-tiles: widths 64,64,64,64,64,58 (starts 0,64,...,320)
#define XT      6
#define STATS_BLOCKS  (XT * 7 * BATCH)          // 1344
#define ROWS_TOTAL    (BATCH * H)               // 12288
#define ROW_BLOCKS    1756                      // ceil(12288 / 7)
#define MAIN_BLOCKS   (STATS_BLOCKS + ROW_BLOCKS)
#define ZB            1184
#define ZGROUPS       (ZB * 4)
#define ZW_BLOCKS     (ZB + 28)
#define MAE_BLOCKS    1512

#define ST_W    72          // sT row stride (floats), padded
#define SP_W    64          // sP row stride (floats)

// ---------------- global scratch (no allocations allowed) ----------------
// All zero at module load; the mae last block re-zeroes everything at the end
// of every run so each graph replay starts from identical state.
__device__ double g_tp[NSHIFT];
__device__ double g_zp[NSHIFT];
__device__ double g_win[NSHIFT * 4];
__device__ double g_sp[32];
__device__ double g_sp2[32];
__device__ double g_abs[32];
__device__ int    g_idx;
__device__ unsigned int g_zcount;
__device__ unsigned int g_done_zw;
__device__ unsigned int g_done_mae;
__device__ float  g_W[4 * NS * BATCH * H];
__device__ int    g_zlist[BATCH * H * H];

// stats inner loop: sliding 7-row window, float2 loads, parity-specialized.
template <bool ODD>
__device__ __forceinline__ void corr_columns(
    const float* sT, const float* sP, int e, int j0, float* acc)
{
    const float2* tb0 = reinterpret_cast<const float2*>(sT + e);
    const float2* tb1 = tb0 + 1;                      // only used when ODD
    const float2* pbs = reinterpret_cast<const float2*>(sP + j0);

    float wa[NS], wb[NS];
#pragma unroll
    for (int k = 0; k < 6; k++) {
        if (ODD) {
            wa[k] = tb0[k * (ST_W / 2)].y;
            wb[k] = tb1[k * (ST_W / 2)].x;
        } else {
            float2 q = tb0[k * (ST_W / 2)];
            wa[k] = q.x; wb[k] = q.y;
        }
    }
    float2 qa = tb0[6 * (ST_W / 2)];
    float2 qb = ODD ? tb1[6 * (ST_W / 2)] : qa;

#pragma unroll 7
    for (int i = 0; i < TILE; i++) {
        if (ODD) { wa[6] = qa.y; wb[6] = qb.x; }
        else     { wa[6] = qa.x; wb[6] = qa.y; }
        float2 pp = pbs[i * (SP_W / 2)];
        if (i + 1 < TILE) {
            qa = tb0[(i + 7) * (ST_W / 2)];
            if (ODD) qb = tb1[(i + 7) * (ST_W / 2)];
        }
#pragma unroll
        for (int u = 0; u < NS; u++) {
            acc[u] = fmaf(wa[u], pp.x, acc[u]);
            acc[u] = fmaf(wb[u], pp.y, acc[u]);
        }
#pragma unroll
        for (int k = 0; k < 6; k++) { wa[k] = wa[k + 1]; wb[k] = wb[k + 1]; }
    }
}

// ======== fused main kernel: stats blocks + rowsum blocks ========
// (224, 6): 42 resident warps/SM (was 28) — enough to hide staging LDG
// latency and LDS scoreboard; regs budget stays 48 (current usage).
__global__ __launch_bounds__(224, 6) void main_kernel(
    const float* __restrict__ pred, const float* __restrict__ target)
{
    __shared__ float sT[60 * ST_W];
    __shared__ float sP[TILE * SP_W];

    const int tid  = threadIdx.x;
    const int lane = tid & 31;
    const int wid  = tid >> 5;

    if (blockIdx.x < STATS_BLOCKS) {
        // ---- dense cross-correlation: warp = v shift, lane = 2 adjacent cols
        const int bid = blockIdx.x;
        const int tx = bid % XT;
        const int ty = (bid / XT) % 7;
        const int b  = bid / (XT * 7);
        const int x0 = tx * 64;
        const int Wd = (tx == XT - 1) ? 58 : 64;   // output cols this tile
        const int y0 = ty * TILE;
        const float* tb = target + (size_t)b * H * H;
        const float* pb = pred   + (size_t)b * H * H;

        // stage target patch rows [y0, y0+60) cols [x0, x0+Wd+6)  (<= 70 cols)
        for (int r = wid; r < 60; r += 7) {
            const float* src = tb + (y0 + r) * H + x0;
            float* dst = &sT[r * ST_W];
            if (lane < Wd + 6) dst[lane] = src[lane];
            int c2 = lane + 32;
            if (c2 < Wd + 6) dst[c2] = src[c2];
            int c3 = lane + 64;
            if (c3 < Wd + 6) dst[c3] = src[c3];
        }
        // stage pred tile rows [y0+3, y0+57) cols [x0+3, x0+3+Wd)
        for (int r = wid; r < TILE; r += 7) {
            const float* src = pb + (y0 + r + 3) * H + (x0 + 3);
            float* dst = &sP[r * SP_W];
            if (lane < Wd) dst[lane] = src[lane];
            int c2 = lane + 32;
            if (c2 < Wd) dst[c2] = src[c2];
        }
        __syncthreads();

        const int v  = wid;           // this warp's v shift
        const int j0 = 2 * lane;      // this lane's pred columns j0, j0+1

        float acc[NS];
#pragma unroll
        for (int u = 0; u < NS; u++) acc[u] = 0.f;

        if (j0 < Wd) {
            const int e = (j0 + v) & ~1;   // even float2 base in sT row
            if (v & 1) corr_columns<true >(sT, sP, e, j0, acc);
            else       corr_columns<false>(sT, sP, e, j0, acc);
        }

#pragma unroll
        for (int u = 0; u < NS; u++) {
            float tp = acc[u];
            for (int o = 16; o; o >>= 1)
                tp += __shfl_xor_sync(0xffffffffu, tp, o);
            if (lane == 0)
                atomicAdd(&g_tp[u * NS + v], (double)tp);
        }
    } else {
        // ---- per-row windowed sums + pred sums + z compaction ----
        const int gw = (blockIdx.x - STATS_BLOCKS) * 7 + wid;
        if (gw >= ROWS_TOTAL) return;
        const int b = gw / H;
        const int y = gw - b * H;
        const float* row = target + ((size_t)b * H + y) * H;

        float s0 = 0.f, s1 = 0.f, s2 = 0.f, s3 = 0.f;
        unsigned zm = 0u;
#pragma unroll
        for (int k = 0; k < 12; k++) {
            int x = lane + 32 * k;
            float t = row[x];
            float m = (t > 5.f) ? 1.f : 0.f;
            s0 += t;
            s1  = fmaf(t, t, s1);
            s2 += m;
            s3  = fmaf(m, t, s3);
            if (t <= 5.f) zm |= (1u << k);
        }

        // compact z pixels: one atomic per row
        {
            unsigned cnt = (unsigned)__popc(zm);
            unsigned pre = cnt;
            for (int o = 1; o < 32; o <<= 1) {
                unsigned n = __shfl_up_sync(0xffffffffu, pre, o);
                if (lane >= o) pre += n;
            }
            unsigned tot  = __shfl_sync(0xffffffffu, pre, 31);
            unsigned excl = pre - cnt;
            unsigned base = 0;
            if (tot) {
                if (lane == 31) base = atomicAdd(&g_zcount, tot);
                base = __shfl_sync(0xffffffffu, base, 31);
                unsigned idx = base + excl;
                unsigned mm = zm;
                while (mm) {
                    int k = __ffs(mm) - 1;
                    mm &= mm - 1;
                    g_zlist[idx++] = (b * H + y) * H + lane + 32 * k;
                }
            }
        }

        for (int o = 16; o; o >>= 1) {
            s0 += __shfl_xor_sync(0xffffffffu, s0, o);
            s1 += __shfl_xor_sync(0xffffffffu, s1, o);
            s2 += __shfl_xor_sync(0xffffffffu, s2, o);
            s3 += __shfl_xor_sync(0xffffffffu, s3, o);
        }

        if (lane == 0) {
            float e[12];
#pragma unroll
            for (int k = 0; k < 6; k++) { e[k] = row[k]; e[6 + k] = row[378 + k]; }
#pragma unroll
            for (int v = 0; v < NS; v++) {
                float L0 = 0.f, L1 = 0.f, L2 = 0.f, L3 = 0.f;
                for (int x = 0; x < v; x++) {
                    float t = e[x];
                    float m = (t > 5.f) ? 1.f : 0.f;
                    L0 += t; L1 += t * t; L2 += m; L3 += m * t;
                }
                float R0 = 0.f, R1 = 0.f, R2 = 0.f, R3 = 0.f;
                for (int k = v; k < 6; k++) {
                    float t = e[6 + k];
                    float m = (t > 5.f) ? 1.f : 0.f;
                    R0 += t; R1 += t * t; R2 += m; R3 += m * t;
                }
                g_W[((0 * NS + v) * BATCH + b) * H + y] = s0 - L0 - R0;
                g_W[((1 * NS + v) * BATCH + b) * H + y] = s1 - L1 - R1;
                g_W[((2 * NS + v) * BATCH + b) * H + y] = s2 - L2 - R2;
                g_W[((3 * NS + v) * BATCH + b) * H + y] = s3 - L3 - R3;
            }
        }

        if (y >= 3 && y < 381) {
            const float* prow = pred + ((size_t)b * H + y) * H;
            float sp = 0.f, sp2 = 0.f;
#pragma unroll
            for (int k = 0; k < 12; k++) {
                int x = 3 + lane + 32 * k;
                if (x < 381) {
                    float p = prow[x];
                    sp += p;
                    sp2 = fmaf(p, p, sp2);
                }
            }
            for (int o = 16; o; o >>= 1) {
                sp  += __shfl_xor_sync(0xffffffffu, sp,  o);
                sp2 += __shfl_xor_sync(0xffffffffu, sp2, o);
            }
            if (lane == 0) {
                atomicAdd(&g_sp [gw & 31], (double)sp);
                atomicAdd(&g_sp2[gw & 31], (double)sp2);
            }
        }
    }
}

// ======== fused: zcorr blocks + winsum blocks + last-block argmin ========
__global__ __launch_bounds__(256) void zw_kernel(const float* __restrict__ pred,
                                                 float* out)
{
    __shared__ float  sAcc[64];
    __shared__ double col[H];
    __shared__ double red[256];
    __shared__ double scmse[64];
    __shared__ int    sidx[64];
    __shared__ int    sLast;

    const int tid = threadIdx.x;

    if (blockIdx.x < ZB) {
        if (tid < 64) sAcc[tid] = 0.f;
        __syncthreads();

        const int sid = tid & 63;
        const int u = sid / NS, v = sid - (sid / NS) * NS;
        const bool active = sid < NSHIFT;
        const int grp = (blockIdx.x * 256 + tid) >> 6;
        const int count = (int)g_zcount;

        float acc = 0.f;
        int zi = grp;
        for (; zi + ZGROUPS < count; zi += 2 * ZGROUPS) {
            int code0 = g_zlist[zi];
            int code1 = g_zlist[zi + ZGROUPS];
            int b0 = code0 / (H * H), r0 = code0 - b0 * (H * H);
            int y0 = r0 / H,          x0 = r0 - y0 * H;
            int b1 = code1 / (H * H), r1 = code1 - b1 * (H * H);
            int y1 = r1 / H,          x1 = r1 - y1 * H;
            if (active) {
                int yy0 = y0 - u, xx0 = x0 - v;
                int yy1 = y1 - u, xx1 = x1 - v;
                bool ok0 = (yy0 >= 0 && yy0 < KK && xx0 >= 0 && xx0 < KK);
                bool ok1 = (yy1 >= 0 && yy1 < KK && xx1 >= 0 && xx1 < KK);
                float p0 = ok0 ? pred[(size_t)b0 * H * H + (yy0 + 3) * H + (xx0 + 3)] : 0.f;
                float p1 = ok1 ? pred[(size_t)b1 * H * H + (yy1 + 3) * H + (xx1 + 3)] : 0.f;
                acc += p0 + p1;
            }
        }
        for (; zi < count; zi += ZGROUPS) {
            int code = g_zlist[zi];
            int b = code / (H * H);
            int r = code - b * (H * H);
            int y = r / H;
            int x = r - y * H;
            if (active) {
                int yy = y - u, xx = x - v;
                if (yy >= 0 && yy < KK && xx >= 0 && xx < KK)
                    acc += pred[(size_t)b * H * H + (yy + 3) * H + (xx + 3)];
            }
        }
        if (active && acc != 0.f) atomicAdd(&sAcc[sid], acc);
        __syncthreads();
        if (tid < NSHIFT && sAcc[tid] != 0.f)
            atomicAdd(&g_zp[tid], (double)sAcc[tid]);
    } else {
        const int wb = blockIdx.x - ZB;
        const int f = wb / NS;
        const int v = wb - f * NS;
        const float* Wfv = &g_W[((f * NS + v) * BATCH) * H];

        for (int y = tid; y < H; y += 256) {
            double s = 0.0;
#pragma unroll 4
            for (int b = 0; b < BATCH; b++)
                s += (double)Wfv[b * H + y];
            col[y] = s;
        }
        __syncthreads();

        double s = col[tid];
        if (tid + 256 < H) s += col[tid + 256];
        red[tid] = s;
        __syncthreads();
        for (int o = 128; o; o >>= 1) {
            if (tid < o) red[tid] += red[tid + o];
            __syncthreads();
        }
        if (tid < NS) {
            double T = red[0];
            for (int y = 0; y < tid; y++) T -= col[y];
            for (int y = tid + KK; y < H; y++) T -= col[y];
            g_win[(tid * NS + v) * 4 + f] = T;
        }
    }

    __threadfence();
    __syncthreads();
    if (tid == 0)
        sLast = (atomicAdd(&g_done_zw, 1u) == (unsigned)(gridDim.x - 1));
    __syncthreads();
    if (!sLast) return;

    volatile double* vtp  = g_tp;
    volatile double* vzp  = g_zp;
    volatile double* vwin = g_win;
    volatile double* vsp  = g_sp;
    volatile double* vsp2 = g_sp2;

    double Sp = 0.0, Sp2 = 0.0;
    for (int k = 0; k < 32; k++) { Sp += vsp[k]; Sp2 += vsp2[k]; }

    if (tid < 64) {
        double c = 1e300;
        if (tid < NSHIFT) {
            double wt  = vwin[tid * 4 + 0];
            double wt2 = vwin[tid * 4 + 1];
            double n   = vwin[tid * 4 + 2];
            double wmt = vwin[tid * 4 + 3];
            double Sd  = wt - Sp;
            double Sd2 = wt2 - 2.0 * vtp[tid] + Sp2;
            double Sm  = wmt - (Sp - vzp[tid]);
            double bb  = Sm / n;
            c = (Sd2 - 2.0 * bb * Sd + NTOT_D * bb * bb) / n;
        }
        scmse[tid] = c; sidx[tid] = tid;
    }
    __syncthreads();
    for (int o = 32; o; o >>= 1) {
        if (tid < o) {
            if (scmse[tid + o] < scmse[tid]) {
                scmse[tid] = scmse[tid + o];
                sidx[tid]  = sidx[tid + o];
            }
        }
        __syncthreads();
    }
    if (tid == 0) {
        g_idx  = sidx[0];
        out[0] = (float)(-10.0 * log10(scmse[0]));
    }
}

// ======== MAE over winning shift + last-block finalize & self-clean ========
__global__ __launch_bounds__(256) void mae_kernel(
    const float* __restrict__ pred, const float* __restrict__ target, float* out)
{
    const int idx = g_idx;
    const int u = idx / NS, v = idx - (idx / NS) * NS;
    const int gw   = blockIdx.x * 8 + (threadIdx.x >> 5);
    const int lane = threadIdx.x & 31;
    const int b    = gw / KK;
    const int i    = gw - b * KK;

    const float* prow = pred   + ((size_t)b * H + i + 3) * H + 3;
    const float* trow = target + ((size_t)b * H + i + u) * H + v;

    float a0 = 0.f, a1 = 0.f;
#pragma unroll
    for (int k = 0; k < 11; k++) {
        int x = lane + 32 * k;
        float d = fabsf(trow[x] - prow[x]);
        if (k & 1) a1 += d; else a0 += d;
    }
    if (lane < 26) {
        int x = lane + 352;
        a1 += fabsf(trow[x] - prow[x]);
    }
    float acc = a0 + a1;
    for (int o = 16; o; o >>= 1) acc += __shfl_xor_sync(0xffffffffu, acc, o);

    __shared__ float ssum[8];
    __shared__ int   sLast;
    const int w = threadIdx.x >> 5;
    if (lane == 0) ssum[w] = acc;
    __syncthreads();
    if (threadIdx.x == 0) {
        float a = 0.f;
#pragma unroll
        for (int k = 0; k < 8; k++) a += ssum[k];
        atomicAdd(&g_abs[blockIdx.x & 31], (double)a);
        __threadfence();
        sLast = (atomicAdd(&g_done_mae, 1u) == (unsigned)(gridDim.x - 1));
        if (sLast) {
            volatile double* ga = g_abs;
            double s = 0.0;
            for (int k = 0; k < 32; k++) s += ga[k];
            out[1] = (float)(s / NTOT_D);
        }
    }
    __syncthreads();
    if (sLast) {
        const int t = threadIdx.x;
        if (t < NSHIFT) { g_tp[t] = 0.0; g_zp[t] = 0.0; }
        if (t < NSHIFT * 4) g_win[t] = 0.0;
        if (t < 32) { g_sp[t] = 0.0; g_sp2[t] = 0.0; g_abs[t] = 0.0; }
        if (t == 0) {
            g_idx = 0;
            g_zcount = 0u;
            g_done_zw = 0u;
            g_done_mae = 0u;
        }
    }
}

extern "C" void kernel_launch(void* const* d_in, const int* in_sizes, int n_in,
                              void* d_out, int out_size) {
    const float* pred   = (const float*)d_in[0];
    const float* target = (const float*)d_in[1];
    float* out = (float*)d_out;

    main_kernel<<<MAIN_BLOCKS, 224>>>(pred, target);
    zw_kernel<<<ZW_BLOCKS, 256>>>(pred, out);
    mae_kernel<<<MAE_BLOCKS, 256>>>(pred, target, out);
}